// round 10
// baseline (speedup 1.0000x reference)
#include <cuda_runtime.h>

#define BATCH 8
#define NPTS  4096
#define MCENT 1024
#define KG    64
#define CIN   64
#define HC    128   // half of C_out

// ---------------- scratch (device globals; no allocation) ----------------
__device__ int    g_idx[BATCH * MCENT];
__device__ float4 g_P1v[BATCH * NPTS * (CIN / 4)];   // W1·p per point
__device__ float4 g_Fov[BATCH * NPTS * (HC / 4)];    // feature-MLP output per point
__device__ float  g_W3t[CIN * HC];                   // W3^T [c][o]

// exact (no-FMA) squared distance, association ((dx^2+dy^2)+dz^2)
__device__ __forceinline__ float sq3(float dx, float dy, float dz) {
    return __fadd_rn(__fadd_rn(__fmul_rn(dx, dx), __fmul_rn(dy, dy)), __fmul_rn(dz, dz));
}

// ======================= prep kernel: fps (blocks 0..7) | W3 transpose (8) | mlp (9..) ==========
// (identical to the round-6 passing version)
__global__ __launch_bounds__(1024) void prep_kernel(
    const float* __restrict__ points, const float* __restrict__ pf,
    const float* __restrict__ pw1, const float* __restrict__ pw3,
    const float* __restrict__ fw1, const float* __restrict__ fb1,
    const float* __restrict__ fw2, const float* __restrict__ fb2,
    const float* __restrict__ fw3, const float* __restrict__ fb3) {
    extern __shared__ float sm[];
    const int tid = threadIdx.x;

    if (blockIdx.x < 8) {
        // ---------------- FPS: 1 CTA / batch ----------------
        float* sx = sm; float* sy = sm + NPTS; float* sz = sm + 2 * NPTS;
        __shared__ unsigned svb[2][32];
        __shared__ unsigned sib[2][32];
        const int b = blockIdx.x;
        const int lane = tid & 31, w = tid >> 5;
        const float* pb = points + b * 3 * NPTS;
        for (int i = tid; i < NPTS; i += 1024) { sx[i] = pb[i]; sy[i] = pb[NPTS + i]; sz[i] = pb[2 * NPTS + i]; }
        __syncthreads();
        const int i0 = tid * 4;
        const float x0 = sx[i0 + 0], y0 = sy[i0 + 0], z0 = sz[i0 + 0];
        const float x1 = sx[i0 + 1], y1 = sy[i0 + 1], z1 = sz[i0 + 1];
        const float x2 = sx[i0 + 2], y2 = sy[i0 + 2], z2 = sz[i0 + 2];
        const float x3 = sx[i0 + 3], y3 = sy[i0 + 3], z3 = sz[i0 + 3];
        float m0 = 1e30f, m1 = 1e30f, m2 = 1e30f, m3 = 1e30f;
        int last = 0;
        for (int s = 0; s < MCENT; s++) {
            if (tid == 0) g_idx[b * MCENT + s] = last;
            const float lx = sx[last], ly = sy[last], lz = sz[last];
            m0 = fminf(m0, sq3(x0 - lx, y0 - ly, z0 - lz));
            m1 = fminf(m1, sq3(x1 - lx, y1 - ly, z1 - lz));
            m2 = fminf(m2, sq3(x2 - lx, y2 - ly, z2 - lz));
            m3 = fminf(m3, sq3(x3 - lx, y3 - ly, z3 - lz));
            float bv = m0; int bi = i0;                 // strictly-greater keeps first max
            if (m1 > bv) { bv = m1; bi = i0 + 1; }
            if (m2 > bv) { bv = m2; bi = i0 + 2; }
            if (m3 > bv) { bv = m3; bi = i0 + 3; }
            const unsigned vb = __float_as_uint(bv);    // nonneg floats: bit order == value order
            const unsigned wmax = __reduce_max_sync(0xffffffffu, vb);
            const unsigned imin = __reduce_min_sync(0xffffffffu, (vb == wmax) ? (unsigned)bi : 0xffffffffu);
            const int par = s & 1;
            if (lane == 0) { svb[par][w] = wmax; sib[par][w] = imin; }
            __syncthreads();
            const unsigned v2 = svb[par][lane];
            const unsigned i2 = sib[par][lane];
            const unsigned gm = __reduce_max_sync(0xffffffffu, v2);
            last = (int)__reduce_min_sync(0xffffffffu, (v2 == gm) ? i2 : 0xffffffffu);
        }
        return;
    }
    if (blockIdx.x == 8) {
        // ---------------- W3 transpose ----------------
        for (int i = tid; i < CIN * HC; i += 1024) {
            const int o = i >> 6, c = i & 63;
            g_W3t[c * HC + o] = pw3[i];
        }
        return;
    }

    // ---------------- pointwise MLP: 32 points / block ----------------
    float* s_fw1t = sm;                 // [c][o] 64x64
    float* s_fw2t = s_fw1t + 4096;      // [c][o] 64x64
    float* s_fw3t = s_fw2t + 4096;      // [c][o] 64x128
    float* s_pw1t = s_fw3t + 8192;      // [d][o] 3x64
    float* s_fb1  = s_pw1t + 192;
    float* s_fb2  = s_fb1 + 64;
    float* s_fb3  = s_fb2 + 64;
    for (int i = tid; i < 4096; i += 1024) {
        const int o = i >> 6, c = i & 63;
        s_fw1t[c * 64 + o] = fw1[i];
        s_fw2t[c * 64 + o] = fw2[i];
    }
    for (int i = tid; i < 8192; i += 1024) { const int o = i >> 6, c = i & 63; s_fw3t[c * 128 + o] = fw3[i]; }
    for (int i = tid; i < 192; i += 1024)  { const int o = i / 3, d = i % 3;  s_pw1t[d * 64 + o] = pw1[i]; }
    if (tid < 64)  { s_fb1[tid] = fb1[tid]; s_fb2[tid] = fb2[tid]; }
    if (tid < 128) s_fb3[tid] = fb3[tid];
    __syncthreads();
    const int warp = tid >> 5, lane = tid & 31;
    const int pidx = (blockIdx.x - 9) * 32 + warp;   // 0..32767
    const int b = pidx >> 12, n = pidx & (NPTS - 1);
    // W1·p (no bias / relu)
    const float px = __ldg(&points[b * 3 * NPTS + n]);
    const float py = __ldg(&points[b * 3 * NPTS + NPTS + n]);
    const float pz = __ldg(&points[b * 3 * NPTS + 2 * NPTS + n]);
    float* p1 = ((float*)g_P1v) + (b * NPTS + n) * CIN;
    p1[lane]      = s_pw1t[lane] * px      + s_pw1t[64 + lane] * py      + s_pw1t[128 + lane] * pz;
    p1[32 + lane] = s_pw1t[32 + lane] * px + s_pw1t[96 + lane] * py      + s_pw1t[160 + lane] * pz;
    // feature MLP
    const float* f = pf + b * CIN * NPTS + n;
    float h1a = s_fb1[lane], h1b = s_fb1[32 + lane];
    #pragma unroll 8
    for (int c = 0; c < 64; c++) {
        const float fc = __ldg(&f[c * NPTS]);
        h1a += s_fw1t[c * 64 + lane] * fc;
        h1b += s_fw1t[c * 64 + 32 + lane] * fc;
    }
    h1a = fmaxf(h1a, 0.f); h1b = fmaxf(h1b, 0.f);
    float h2a = s_fb2[lane], h2b = s_fb2[32 + lane];
    #pragma unroll 8
    for (int c = 0; c < 64; c++) {
        const float src = (c < 32) ? h1a : h1b;
        const float v = __shfl_sync(0xffffffffu, src, c & 31);
        h2a += s_fw2t[c * 64 + lane] * v;
        h2b += s_fw2t[c * 64 + 32 + lane] * v;
    }
    h2a = fmaxf(h2a, 0.f); h2b = fmaxf(h2b, 0.f);
    float o0 = s_fb3[lane], o1 = s_fb3[32 + lane], o2v = s_fb3[64 + lane], o3 = s_fb3[96 + lane];
    #pragma unroll 8
    for (int c = 0; c < 64; c++) {
        const float src = (c < 32) ? h2a : h2b;
        const float v = __shfl_sync(0xffffffffu, src, c & 31);
        o0  += s_fw3t[c * 128 + lane] * v;
        o1  += s_fw3t[c * 128 + 32 + lane] * v;
        o2v += s_fw3t[c * 128 + 64 + lane] * v;
        o3  += s_fw3t[c * 128 + 96 + lane] * v;
    }
    float* fo = ((float*)g_Fov) + (b * NPTS + n) * HC;
    fo[lane] = o0; fo[32 + lane] = o1; fo[64 + lane] = o2v; fo[96 + lane] = o3;
}

// ======================= K_group: inline ball query + L2/L3 + max (512 thr) =======================
__global__ __launch_bounds__(512, 4) void group_kernel(
    const float* __restrict__ points,
    const float* __restrict__ pw2, const float* __restrict__ pb1,
    const float* __restrict__ pb2, const float* __restrict__ pb3,
    float* __restrict__ out) {
    __shared__ __align__(16) float sW2t[4096];    // W2^T [c][o] 64x64
    __shared__ __align__(16) float sH2t[4096];    // h2^T [c][k] 64x64
    __shared__ __align__(16) float sQ[64];        // b1 - W1·centroid
    __shared__ float    sRed[384];
    __shared__ int      sSel[64];
    __shared__ unsigned sMask[128];
    const int g = blockIdx.x, b = g >> 10, m = g & 1023;
    const int tid = threadIdx.x, lane = tid & 31, w = tid >> 5;

    for (int i = tid; i < 4096; i += 512) { const int o = i >> 6, c = i & 63; sW2t[c * 64 + o] = pw2[i]; }

    const int cidx = g_idx[g];
    const float cx = __ldg(&points[b * 3 * NPTS + cidx]);
    const float cy = __ldg(&points[b * 3 * NPTS + NPTS + cidx]);
    const float cz = __ldg(&points[b * 3 * NPTS + 2 * NPTS + cidx]);
    if (tid < 3) out[b * 3 * MCENT + m * 3 + tid] = (tid == 0) ? cx : ((tid == 1) ? cy : cz);
    if (tid < 64) sQ[tid] = __ldg(&pb1[tid]) - ((const float*)g_P1v)[(b * NPTS + cidx) * CIN + tid];

    // ---- ball query: 16 warps x 8 chunks -> masks; warp 0 ordered selection ----
    {
        const float* px_ = points + b * 3 * NPTS;
        #pragma unroll
        for (int c = 0; c < 8; c++) {
            const int i = (w * 8 + c) * 32 + lane;
            const float d2 = sq3(cx - __ldg(&px_[i]), cy - __ldg(&px_[NPTS + i]), cz - __ldg(&px_[2 * NPTS + i]));
            const unsigned msk = __ballot_sync(0xffffffffu, d2 <= 0.04f);   // f32(0.2*0.2)
            if (lane == 0) sMask[w * 8 + c] = msk;
        }
    }
    __syncthreads();
    if (w == 0) {
        int cnt = 0, first = 0; bool gotf = false;
        const unsigned lt = (1u << lane) - 1u;
        for (int ch = 0; ch < 128; ch++) {
            const unsigned msk = sMask[ch];
            if (!gotf && msk) { first = ch * 32 + __ffs(msk) - 1; gotf = true; }
            const int rank = __popc(msk & lt);
            if (((msk >> lane) & 1u) && cnt + rank < KG) sSel[cnt + rank] = ch * 32 + lane;
            cnt += __popc(msk);
            if (cnt >= KG) break;
        }
        for (int j = cnt + lane; j < KG; j += 32) sSel[j] = first;   // pad with smallest hit
    }
    __syncthreads();

    // ---- Phase A: h2 = relu(W2·relu(p1[n] + q) + b2), thread (k, oct) -> 8 channels ----
    {
        const int k = tid & 63, obase = (tid >> 6) * 8;
        const int n = sSel[k];
        const float4* p1row = (const float4*)(((const float*)g_P1v) + (b * NPTS + n) * CIN);
        const float4* sQ4 = (const float4*)sQ;
        float acc[8];
        #pragma unroll
        for (int j = 0; j < 8; j++) acc[j] = __ldg(&pb2[obase + j]);
        #pragma unroll 4
        for (int c4 = 0; c4 < 16; c4++) {
            const float4 p = __ldg(&p1row[c4]);
            const float4 qv = sQ4[c4];
            float a[4];
            a[0] = fmaxf(p.x + qv.x, 0.f); a[1] = fmaxf(p.y + qv.y, 0.f);
            a[2] = fmaxf(p.z + qv.z, 0.f); a[3] = fmaxf(p.w + qv.w, 0.f);
            #pragma unroll
            for (int cc = 0; cc < 4; cc++) {
                const float4* wr = (const float4*)(sW2t + (4 * c4 + cc) * 64 + obase);
                const float4 w0 = wr[0], w1 = wr[1];
                acc[0] += w0.x * a[cc]; acc[1] += w0.y * a[cc];
                acc[2] += w0.z * a[cc]; acc[3] += w0.w * a[cc];
                acc[4] += w1.x * a[cc]; acc[5] += w1.y * a[cc];
                acc[6] += w1.z * a[cc]; acc[7] += w1.w * a[cc];
            }
        }
        #pragma unroll
        for (int j = 0; j < 8; j++) sH2t[(obase + j) * 64 + k] = fmaxf(acc[j], 0.f);
    }
    __syncthreads();

    float* o2 = out + BATCH * 3 * MCENT + b * (2 * HC * MCENT);
    // ---- Phase B: thread (og, kg) = 4 outputs x 4 neighbors; W3^T via L1, h2 via smem ----
    {
        const int og = tid >> 4, kg = tid & 15;
        float a0[4], a1[4], a2[4], a3[4];
        #pragma unroll
        for (int j = 0; j < 4; j++) { a0[j] = 0.f; a1[j] = 0.f; a2[j] = 0.f; a3[j] = 0.f; }
        const float4* hP = (const float4*)(sH2t + kg * 4);
        const float4* wP = (const float4*)(g_W3t + og * 4);
        #pragma unroll 8
        for (int c = 0; c < 64; c++) {
            const float4 h  = hP[c * 16];
            const float4 wv = __ldg(&wP[c * 32]);
            a0[0] += wv.x * h.x; a0[1] += wv.y * h.x; a0[2] += wv.z * h.x; a0[3] += wv.w * h.x;
            a1[0] += wv.x * h.y; a1[1] += wv.y * h.y; a1[2] += wv.z * h.y; a1[3] += wv.w * h.y;
            a2[0] += wv.x * h.z; a2[1] += wv.y * h.z; a2[2] += wv.z * h.z; a2[3] += wv.w * h.z;
            a3[0] += wv.x * h.w; a3[1] += wv.y * h.w; a3[2] += wv.z * h.w; a3[3] += wv.w * h.w;
        }
        #pragma unroll
        for (int j = 0; j < 4; j++) {
            float v = fmaxf(fmaxf(a0[j], a1[j]), fmaxf(a2[j], a3[j]));
            v = fmaxf(v, __shfl_down_sync(0xffffffffu, v, 8, 16));
            v = fmaxf(v, __shfl_down_sync(0xffffffffu, v, 4, 16));
            v = fmaxf(v, __shfl_down_sync(0xffffffffu, v, 2, 16));
            v = fmaxf(v, __shfl_down_sync(0xffffffffu, v, 1, 16));
            if (kg == 0) {
                const int o = og * 4 + j;
                o2[(HC + o) * MCENT + m] = v + __ldg(&pb3[o]);   // p_out -> channels [128,256)
            }
        }
    }
    // ---- f_out (channels [0,128)): gather-max of feature-MLP outputs ----
    {
        const int o = tid & 127, qt = tid >> 7;
        const float* fb_ = ((const float*)g_Fov) + b * NPTS * HC + o;
        float v = -3.4e38f;
        #pragma unroll
        for (int kk = 0; kk < 16; kk++) v = fmaxf(v, __ldg(&fb_[sSel[qt * 16 + kk] * HC]));
        if (qt) sRed[(qt - 1) * 128 + o] = v;
        __syncthreads();
        if (!qt) o2[o * MCENT + m] = fmaxf(fmaxf(v, sRed[o]), fmaxf(sRed[128 + o], sRed[256 + o]));
    }
}

// ======================= launch =======================
extern "C" void kernel_launch(void* const* d_in, const int* in_sizes, int n_in,
                              void* d_out, int out_size) {
    const float* points = (const float*)d_in[0];
    const float* pfeat  = (const float*)d_in[1];
    const float* pw1 = (const float*)d_in[2];  const float* pb1 = (const float*)d_in[3];
    const float* pw2 = (const float*)d_in[4];  const float* pb2 = (const float*)d_in[5];
    const float* pw3 = (const float*)d_in[6];  const float* pb3 = (const float*)d_in[7];
    const float* fw1 = (const float*)d_in[8];  const float* fb1 = (const float*)d_in[9];
    const float* fw2 = (const float*)d_in[10]; const float* fb2 = (const float*)d_in[11];
    const float* fw3 = (const float*)d_in[12]; const float* fb3 = (const float*)d_in[13];
    float* out = (float*)d_out;

    cudaFuncSetAttribute(prep_kernel, cudaFuncAttributeMaxDynamicSharedMemorySize, 67328);

    prep_kernel<<<8 + 1 + 1024, 1024, 67328>>>(points, pfeat, pw1, pw3,
                                               fw1, fb1, fw2, fb2, fw3, fb3);
    group_kernel<<<BATCH * MCENT, 512>>>(points, pw2, pb1, pb2, pb3, out);
}